// round 12
// baseline (speedup 1.0000x reference)
#include <cuda_runtime.h>
#include <math.h>

// Problem constants (fixed by the dataset)
#define NB   8192      // batch rows
#define NV   32000     // vocab (row length)
#define NK   5         // negatives per row
#define NS   100       // sampling-domain columns of prob
#define EPSF 1e-10f

#define NCTA 128       // 128 CTAs x 64 threads = 8192 = one thread per row
#define NTHR 64

// Scratch for the fused cross-block reduction (no allocs allowed)
__device__ float g_partial[NCTA];
__device__ int   g_ticket = 0;   // re-armed to 0 by the last block each call

// FINAL (best-measured, R9 variant, 8.54us):
// The detached row-max shift cancels exactly in out = terms / sum(terms),
// so the 1.048 GB streaming max over yHat is mathematically unnecessary —
// the loss needs only 6 gathered logits per row (ind[] < 100, plus the
// target column y[b]) and 5 prob-table entries. The kernel is pure
// scattered-load latency + a fenceless release-ticket cross-CTA reduction;
// measured time sits at the graph-replay launch floor, not on any HW pipe.
__global__ __launch_bounds__(NTHR, 1) void blackout_fused_kernel(
    const float* __restrict__ yHat,
    const float* __restrict__ prob,
    const int*   __restrict__ y,
    const int*   __restrict__ ind,
    float*       __restrict__ out)
{
    const int b = blockIdx.x * NTHR + threadIdx.x;   // 0..8191, exact cover

    // ---- level 0: coalesced index loads (L2-hot across graph replays) ----
    const int yb = __ldg(&y[b]);
    int id[NK];
    #pragma unroll
    for (int j = 0; j < NK; ++j) id[j] = __ldg(&ind[b * NK + j]);

    // ---- level 1: ALL 11 data gathers issued before any math ----
    const float* __restrict__ prow = prob + (long long)yb * NS;
    const float* __restrict__ rowf = yHat + (long long)b * NV;

    float pr[NK], cj[NK];
    const float tg = __ldg(&rowf[yb]);            // truly-random target gather
    #pragma unroll
    for (int j = 0; j < NK; ++j) pr[j] = __ldg(&prow[id[j]]);
    #pragma unroll
    for (int j = 0; j < NK; ++j) cj[j] = __ldg(&rowf[id[j]]);

    // ---- math tail (MUFU intrinsics; max shift cancels in the ratio) ----
    float p[NK], q = INFINITY;
    #pragma unroll
    for (int j = 0; j < NK; ++j) {
        p[j] = __frcp_rn(pr[j]);
        q = fminf(q, p[j]);
    }

    float t[NK];
    float t0 = q * __expf(tg);
    float S  = t0;
    #pragma unroll
    for (int j = 0; j < NK; ++j) {
        t[j] = p[j] * __expf(cj[j]);
        S += t[j];
    }
    const float inv = 1.0f / S;

    float acc = __logf(t0 * inv + EPSF);          // log(out_0 + eps)
    #pragma unroll
    for (int j = 0; j < NK; ++j)
        acc += __logf(1.0f - t[j] * inv + EPSF);  // log(1 - out_j + eps)

    // ---- deterministic block reduction (64 -> 1) ----
    __shared__ float sw[2];
    #pragma unroll
    for (int o = 16; o; o >>= 1) acc += __shfl_xor_sync(0xffffffffu, acc, o);
    const int lane = threadIdx.x & 31;
    const int wid  = threadIdx.x >> 5;
    if (lane == 0) sw[wid] = acc;
    __syncthreads();

    __shared__ int s_last;
    if (threadIdx.x == 0) {
        g_partial[blockIdx.x] = sw[0] + sw[1];
        // release-atomic ticket: orders the partial store without a separate
        // MEMBAR.GPU round-trip. Last block to arrive does the final sum.
        int t_;
        asm volatile("atom.add.release.gpu.u32 %0, [%1], 1;"
                     : "=r"(t_) : "l"(&g_ticket) : "memory");
        s_last = (t_ == NCTA - 1);
    }
    __syncthreads();

    if (s_last && threadIdx.x < 32) {
        // acquire fence pairs with the producers' release-atomics; then
        // volatile reads bypass this SM's (non-coherent) L1. Fixed order ->
        // deterministic.
        if (threadIdx.x == 0)
            asm volatile("fence.acquire.gpu;" ::: "memory");
        __syncwarp();
        volatile float* gp = g_partial;
        float v = 0.0f;
        #pragma unroll
        for (int k = 0; k < NCTA / 32; ++k)      // 128 partials, 4 per lane
            v += gp[k * 32 + threadIdx.x];
        #pragma unroll
        for (int o = 16; o; o >>= 1) v += __shfl_xor_sync(0xffffffffu, v, o);
        if (threadIdx.x == 0) {
            out[0] = -v / (float)(NB * (NK + 1));
            g_ticket = 0;                        // re-arm for next graph replay
        }
    }
}

extern "C" void kernel_launch(void* const* d_in, const int* in_sizes, int n_in,
                              void* d_out, int out_size)
{
    const float* yHat = (const float*)d_in[0];   // [8192, 32000] f32
    const float* prob = (const float*)d_in[1];   // [32000, 100] f32
    const int*   y    = (const int*)d_in[2];     // [8192] i32
    const int*   ind  = (const int*)d_in[3];     // [8192, 5] i32
    float* out = (float*)d_out;

    blackout_fused_kernel<<<NCTA, NTHR>>>(yHat, prob, y, ind, out);
}

// round 17
// speedup vs baseline: 1.0295x; 1.0295x over previous
#include <cuda_runtime.h>
#include <math.h>

// Problem constants (fixed by the dataset)
#define NB   8192      // batch rows
#define NV   32000     // vocab (row length)
#define NK   5         // negatives per row
#define NS   100       // sampling-domain columns of prob
#define EPSF 1e-10f

#define NCTA 128       // 128 CTAs x 64 threads = 8192 = one thread per row
#define NTHR 64

// Scratch for the fused cross-block reduction (no allocs allowed)
__device__ float g_partial[NCTA];
__device__ int   g_ticket = 0;   // re-armed to 0 by the last block each call

// FINAL (best-measured variant, 8.54us):
// The detached row-max shift cancels exactly in out = terms / sum(terms),
// so the 1.048 GB streaming max over yHat is mathematically unnecessary —
// the loss needs only 6 gathered logits per row (ind[] < 100, plus the
// target column y[b]) and 5 prob-table entries. The kernel is pure
// scattered-load latency + a fenceless release-ticket cross-CTA reduction;
// measured time sits at the graph-replay launch floor, not on any HW pipe.
__global__ __launch_bounds__(NTHR, 1) void blackout_fused_kernel(
    const float* __restrict__ yHat,
    const float* __restrict__ prob,
    const int*   __restrict__ y,
    const int*   __restrict__ ind,
    float*       __restrict__ out)
{
    const int b = blockIdx.x * NTHR + threadIdx.x;   // 0..8191, exact cover

    // ---- level 0: coalesced index loads (L2-hot across graph replays) ----
    const int yb = __ldg(&y[b]);
    int id[NK];
    #pragma unroll
    for (int j = 0; j < NK; ++j) id[j] = __ldg(&ind[b * NK + j]);

    // ---- level 1: ALL 11 data gathers issued before any math ----
    const float* __restrict__ prow = prob + (long long)yb * NS;
    const float* __restrict__ rowf = yHat + (long long)b * NV;

    float pr[NK], cj[NK];
    const float tg = __ldg(&rowf[yb]);            // truly-random target gather
    #pragma unroll
    for (int j = 0; j < NK; ++j) pr[j] = __ldg(&prow[id[j]]);
    #pragma unroll
    for (int j = 0; j < NK; ++j) cj[j] = __ldg(&rowf[id[j]]);

    // ---- math tail (MUFU intrinsics; max shift cancels in the ratio) ----
    float p[NK], q = INFINITY;
    #pragma unroll
    for (int j = 0; j < NK; ++j) {
        p[j] = __frcp_rn(pr[j]);
        q = fminf(q, p[j]);
    }

    float t[NK];
    float t0 = q * __expf(tg);
    float S  = t0;
    #pragma unroll
    for (int j = 0; j < NK; ++j) {
        t[j] = p[j] * __expf(cj[j]);
        S += t[j];
    }
    const float inv = 1.0f / S;

    float acc = __logf(t0 * inv + EPSF);          // log(out_0 + eps)
    #pragma unroll
    for (int j = 0; j < NK; ++j)
        acc += __logf(1.0f - t[j] * inv + EPSF);  // log(1 - out_j + eps)

    // ---- deterministic block reduction (64 -> 1) ----
    __shared__ float sw[2];
    #pragma unroll
    for (int o = 16; o; o >>= 1) acc += __shfl_xor_sync(0xffffffffu, acc, o);
    const int lane = threadIdx.x & 31;
    const int wid  = threadIdx.x >> 5;
    if (lane == 0) sw[wid] = acc;
    __syncthreads();

    __shared__ int s_last;
    if (threadIdx.x == 0) {
        g_partial[blockIdx.x] = sw[0] + sw[1];
        // release-atomic ticket: orders the partial store without a separate
        // MEMBAR.GPU round-trip. Last block to arrive does the final sum.
        int t_;
        asm volatile("atom.add.release.gpu.u32 %0, [%1], 1;"
                     : "=r"(t_) : "l"(&g_ticket) : "memory");
        s_last = (t_ == NCTA - 1);
    }
    __syncthreads();

    if (s_last && threadIdx.x < 32) {
        // acquire fence pairs with the producers' release-atomics; then
        // volatile reads bypass this SM's (non-coherent) L1. Fixed order ->
        // deterministic.
        if (threadIdx.x == 0)
            asm volatile("fence.acquire.gpu;" ::: "memory");
        __syncwarp();
        volatile float* gp = g_partial;
        float v = 0.0f;
        #pragma unroll
        for (int k = 0; k < NCTA / 32; ++k)      // 128 partials, 4 per lane
            v += gp[k * 32 + threadIdx.x];
        #pragma unroll
        for (int o = 16; o; o >>= 1) v += __shfl_xor_sync(0xffffffffu, v, o);
        if (threadIdx.x == 0) {
            out[0] = -v / (float)(NB * (NK + 1));
            g_ticket = 0;                        // re-arm for next graph replay
        }
    }
}

extern "C" void kernel_launch(void* const* d_in, const int* in_sizes, int n_in,
                              void* d_out, int out_size)
{
    const float* yHat = (const float*)d_in[0];   // [8192, 32000] f32
    const float* prob = (const float*)d_in[1];   // [32000, 100] f32
    const int*   y    = (const int*)d_in[2];     // [8192] i32
    const int*   ind  = (const int*)d_in[3];     // [8192, 5] i32
    float* out = (float*)d_out;

    blackout_fused_kernel<<<NCTA, NTHR>>>(yHat, prob, y, ind, out);
}